// round 2
// baseline (speedup 1.0000x reference)
#include <cuda_runtime.h>
#include <cstdint>
#include <cstddef>

#define T_TOK 1024
#define HDIM  2048
#define IDIM  768
#define NEXP  64
#define TOPK  4
#define MT    64      // m-tile (tokens per expert tile)

// ---------------- static device scratch (no allocations) ----------------
__device__ float g_logits[T_TOK * NEXP];
__device__ int   g_counts[NEXP];
__device__ int   g_offs[NEXP];
__device__ int   g_cursor[NEXP];
__device__ int   g_topi[T_TOK * TOPK];
__device__ float g_topw[T_TOK * TOPK];
__device__ int   g_tok[T_TOK * TOPK];    // compact token list per expert
__device__ float g_wt[T_TOK * TOPK];     // route weight per slot
__device__ int   g_slot[T_TOK * TOPK];   // token -> its 4 slot indices
__device__ int   g_work[128];            // (e<<6)|mt
__device__ int   g_nwork;
__device__ float g_Y [(size_t)T_TOK * TOPK * IDIM];   // 12.6 MB
__device__ float g_Y2[(size_t)T_TOK * TOPK * HDIM];   // 33.6 MB

// ---------------- helpers ----------------
__device__ __forceinline__ uint32_t f2tf(float f) {
    uint32_t r;
    asm("cvt.rna.tf32.f32 %0, %1;" : "=r"(r) : "f"(f));
    return r;
}
__device__ __forceinline__ void mma8(float* c, const uint32_t* a, const uint32_t* b) {
    asm volatile(
        "mma.sync.aligned.m16n8k8.row.col.f32.tf32.tf32.f32 "
        "{%0,%1,%2,%3}, {%4,%5,%6,%7}, {%8,%9}, {%0,%1,%2,%3};"
        : "+f"(c[0]), "+f"(c[1]), "+f"(c[2]), "+f"(c[3])
        : "r"(a[0]), "r"(a[1]), "r"(a[2]), "r"(a[3]), "r"(b[0]), "r"(b[1]));
}

// ---------------- init: zero expert counts ----------------
__global__ void init_kernel() {
    if (threadIdx.x < NEXP) g_counts[threadIdx.x] = 0;
}

// ---------------- router: fp32 logits = X @ Gw^T (deterministic) ---------
__global__ __launch_bounds__(256) void router_kernel(const float* __restrict__ x,
                                                     const float* __restrict__ gw) {
    __shared__ float Xs[16][72];
    __shared__ float Wt[64][72];
    const int tt = blockIdx.x;          // 64 tiles of 16 tokens
    const int tid = threadIdx.x;
    const int t = tid & 15, eg = tid >> 4;   // 16 expert groups of 4
    float acc[4] = {0.f, 0.f, 0.f, 0.f};

    for (int kc = 0; kc < HDIM; kc += 64) {
        {
            int r = tid >> 4, q = tid & 15;
            float4 v = *(const float4*)(x + (size_t)(tt * 16 + r) * HDIM + kc + q * 4);
            *(float4*)&Xs[r][q * 4] = v;
        }
#pragma unroll
        for (int it = 0; it < 4; it++) {
            int s = it * 256 + tid;
            int e = s >> 4, q = s & 15;
            float4 v = *(const float4*)(gw + (size_t)e * HDIM + kc + q * 4);
            *(float4*)&Wt[e][q * 4] = v;
        }
        __syncthreads();
#pragma unroll
        for (int k = 0; k < 64; k += 4) {
            float4 a = *(const float4*)&Xs[t][k];
#pragma unroll
            for (int j = 0; j < 4; j++) {
                float4 b = *(const float4*)&Wt[eg * 4 + j][k];
                acc[j] += a.x * b.x + a.y * b.y + a.z * b.z + a.w * b.w;
            }
        }
        __syncthreads();
    }
    int tok = tt * 16 + t;
#pragma unroll
    for (int j = 0; j < 4; j++) g_logits[tok * NEXP + eg * 4 + j] = acc[j];
}

// ---------- top-4 + softmax-over-top4 (== softmax -> topk -> renorm) -----
__global__ void topk_kernel() {
    int t = blockIdx.x * blockDim.x + threadIdx.x;
    if (t >= T_TOK) return;
    float v0 = -1e30f, v1 = -1e30f, v2 = -1e30f, v3 = -1e30f;
    int i0 = 0, i1 = 0, i2 = 0, i3 = 0;
    const float* L = &g_logits[t * NEXP];
    for (int e = 0; e < NEXP; e++) {
        float l = L[e];
        if (l > v3) {
            if (l > v2) {
                v3 = v2; i3 = i2;
                if (l > v1) {
                    v2 = v1; i2 = i1;
                    if (l > v0) { v1 = v0; i1 = i0; v0 = l; i0 = e; }
                    else        { v1 = l;  i1 = e; }
                } else { v2 = l; i2 = e; }
            } else { v3 = l; i3 = e; }
        }
    }
    float e0 = 1.f;
    float e1 = expf(v1 - v0), e2 = expf(v2 - v0), e3 = expf(v3 - v0);
    float inv = 1.f / (e0 + e1 + e2 + e3);
    int   ii[4] = {i0, i1, i2, i3};
    float ww[4] = {e0 * inv, e1 * inv, e2 * inv, e3 * inv};
#pragma unroll
    for (int j = 0; j < TOPK; j++) {
        g_topi[t * TOPK + j] = ii[j];
        g_topw[t * TOPK + j] = ww[j];
        atomicAdd(&g_counts[ii[j]], 1);
    }
}

// ---------------- scan: offsets + tile work list --------------------------
__global__ void scan_kernel() {
    if (threadIdx.x == 0 && blockIdx.x == 0) {
        int off = 0, w = 0;
        for (int e = 0; e < NEXP; e++) {
            g_offs[e] = off;
            g_cursor[e] = 0;
            int n = g_counts[e];
            off += n;
            int tiles = (n + MT - 1) / MT;
            for (int mt = 0; mt < tiles; mt++) g_work[w++] = (e << 6) | mt;
        }
        g_nwork = w;
    }
}

// ---------------- fill compact per-expert token/weight lists --------------
__global__ void fill_kernel() {
    int t = blockIdx.x * blockDim.x + threadIdx.x;
    if (t >= T_TOK) return;
#pragma unroll
    for (int j = 0; j < TOPK; j++) {
        int e = g_topi[t * TOPK + j];
        int p = atomicAdd(&g_cursor[e], 1);
        int idx = g_offs[e] + p;
        g_tok[idx] = t;
        g_wt[idx]  = g_topw[t * TOPK + j];
        g_slot[t * TOPK + j] = idx;
    }
}

// ------ GEMM1: Y[slot][0:768] = silu(X@Wg^T) * (X@Wu^T) * route_w, tf32 ---
// block = 128 thr (4 warps), C tile m64 x (gate64 + up64), K chunks of 32
__global__ __launch_bounds__(128, 3) void gemm1_kernel(const float* __restrict__ x,
                                                       const float* __restrict__ gup) {
    const int widx = blockIdx.y;
    if (widx >= g_nwork) return;
    const int jt = blockIdx.x;                 // 0..11
    const int packed = g_work[widx];
    const int e = packed >> 6, mt = packed & 63;
    const int n_e = g_counts[e];
    const int base = g_offs[e] + mt * MT;
    int m_cnt = n_e - mt * MT; if (m_cnt > MT) m_cnt = MT;

    __shared__ uint32_t Xs[64][36];
    __shared__ uint32_t Bg[64][36];
    __shared__ uint32_t Bu[64][36];
    __shared__ int   s_tok[64];
    __shared__ float s_wt[64];

    const int tid = threadIdx.x;
    const int w = tid >> 5, lane = tid & 31;
    if (tid < 64) {
        int tk = 0; float wt = 0.f;
        if (tid < m_cnt) { tk = g_tok[base + tid]; wt = g_wt[base + tid]; }
        s_tok[tid] = tk; s_wt[tid] = wt;
    }
    __syncthreads();

    float cg[4][2][4], cu[4][2][4];
#pragma unroll
    for (int a = 0; a < 4; a++)
#pragma unroll
        for (int b = 0; b < 2; b++)
#pragma unroll
            for (int c = 0; c < 4; c++) { cg[a][b][c] = 0.f; cu[a][b][c] = 0.f; }

    const float* wg = gup + (size_t)e * (2 * IDIM) * HDIM;
    const int lr = lane >> 2, lc = lane & 3;

    for (int kc = 0; kc < HDIM; kc += 32) {
        float4 xa[4];
#pragma unroll
        for (int i = 0; i < 4; i++) {
            int s = i * 128 + tid; int r = s >> 3, q = s & 7;
            xa[i] = *(const float4*)(x + (size_t)s_tok[r] * HDIM + kc + q * 4);
        }
        float4 wb[8];
#pragma unroll
        for (int i = 0; i < 8; i++) {
            int s = i * 128 + tid; int r = s >> 3, q = s & 7;
            int jrow = (r < 64) ? (jt * 64 + r) : (IDIM + jt * 64 + (r - 64));
            wb[i] = *(const float4*)(wg + (size_t)jrow * HDIM + kc + q * 4);
        }
        __syncthreads();
#pragma unroll
        for (int i = 0; i < 4; i++) {
            int s = i * 128 + tid; int r = s >> 3, q = s & 7;
            Xs[r][q * 4 + 0] = f2tf(xa[i].x); Xs[r][q * 4 + 1] = f2tf(xa[i].y);
            Xs[r][q * 4 + 2] = f2tf(xa[i].z); Xs[r][q * 4 + 3] = f2tf(xa[i].w);
        }
#pragma unroll
        for (int i = 0; i < 8; i++) {
            int s = i * 128 + tid; int r = s >> 3, q = s & 7;
            uint32_t* dst = (r < 64) ? &Bg[r][q * 4] : &Bu[r - 64][q * 4];
            dst[0] = f2tf(wb[i].x); dst[1] = f2tf(wb[i].y);
            dst[2] = f2tf(wb[i].z); dst[3] = f2tf(wb[i].w);
        }
        __syncthreads();
#pragma unroll
        for (int kk = 0; kk < 32; kk += 8) {
            uint32_t a[4][4];
#pragma unroll
            for (int mi = 0; mi < 4; mi++) {
                a[mi][0] = Xs[mi * 16 + lr][kk + lc];
                a[mi][1] = Xs[mi * 16 + 8 + lr][kk + lc];
                a[mi][2] = Xs[mi * 16 + lr][kk + 4 + lc];
                a[mi][3] = Xs[mi * 16 + 8 + lr][kk + 4 + lc];
            }
            uint32_t bg[2][2], bu[2][2];
#pragma unroll
            for (int ni = 0; ni < 2; ni++) {
                int nr = w * 16 + ni * 8 + lr;
                bg[ni][0] = Bg[nr][kk + lc]; bg[ni][1] = Bg[nr][kk + 4 + lc];
                bu[ni][0] = Bu[nr][kk + lc]; bu[ni][1] = Bu[nr][kk + 4 + lc];
            }
#pragma unroll
            for (int mi = 0; mi < 4; mi++)
#pragma unroll
                for (int ni = 0; ni < 2; ni++) {
                    mma8(cg[mi][ni], a[mi], bg[ni]);
                    mma8(cu[mi][ni], a[mi], bu[ni]);
                }
        }
        __syncthreads();
    }

    // epilogue: silu(g)*u*route_w -> Y
#pragma unroll
    for (int mi = 0; mi < 4; mi++)
#pragma unroll
        for (int ni = 0; ni < 2; ni++) {
            int col = jt * 64 + w * 16 + ni * 8 + 2 * lc;
#pragma unroll
            for (int h = 0; h < 2; h++) {
                int row = mi * 16 + lr + h * 8;
                if (row < m_cnt) {
                    float wt = s_wt[row];
                    float g0 = cg[mi][ni][h * 2],     g1 = cg[mi][ni][h * 2 + 1];
                    float u0 = cu[mi][ni][h * 2],     u1 = cu[mi][ni][h * 2 + 1];
                    float y0 = g0 / (1.f + __expf(-g0)) * u0 * wt;
                    float y1 = g1 / (1.f + __expf(-g1)) * u1 * wt;
                    *(float2*)&g_Y[(size_t)(base + row) * IDIM + col] = make_float2(y0, y1);
                }
            }
        }
}

// ------ GEMM2: Y2[slot][0:2048] = Y @ W2^T, tf32 --------------------------
// block = 128 thr (4 warps), C tile m64 x n128, K = 768 in chunks of 32
__global__ __launch_bounds__(128, 3) void gemm2_kernel(const float* __restrict__ down) {
    const int widx = blockIdx.y;
    if (widx >= g_nwork) return;
    const int ht = blockIdx.x;                 // 0..15
    const int packed = g_work[widx];
    const int e = packed >> 6, mt = packed & 63;
    const int n_e = g_counts[e];
    const int base = g_offs[e] + mt * MT;
    int m_cnt = n_e - mt * MT; if (m_cnt > MT) m_cnt = MT;

    __shared__ uint32_t Ys[64][36];
    __shared__ uint32_t Bs[128][36];

    const int tid = threadIdx.x;
    const int w = tid >> 5, lane = tid & 31;
    const int lr = lane >> 2, lc = lane & 3;

    float c[4][4][4];
#pragma unroll
    for (int a = 0; a < 4; a++)
#pragma unroll
        for (int b = 0; b < 4; b++)
#pragma unroll
            for (int k = 0; k < 4; k++) c[a][b][k] = 0.f;

    const float* wd = down + (size_t)e * HDIM * IDIM;

    for (int kc = 0; kc < IDIM; kc += 32) {
        float4 ya[4];
#pragma unroll
        for (int i = 0; i < 4; i++) {
            int s = i * 128 + tid; int r = s >> 3, q = s & 7;
            int slot = base + r; if (slot > T_TOK * TOPK - 1) slot = T_TOK * TOPK - 1;
            ya[i] = *(const float4*)(&g_Y[(size_t)slot * IDIM + kc + q * 4]);
        }
        float4 wb[8];
#pragma unroll
        for (int i = 0; i < 8; i++) {
            int s = i * 128 + tid; int r = s >> 3, q = s & 7;
            wb[i] = *(const float4*)(wd + (size_t)(ht * 128 + r) * IDIM + kc + q * 4);
        }
        __syncthreads();
#pragma unroll
        for (int i = 0; i < 4; i++) {
            int s = i * 128 + tid; int r = s >> 3, q = s & 7;
            Ys[r][q * 4 + 0] = f2tf(ya[i].x); Ys[r][q * 4 + 1] = f2tf(ya[i].y);
            Ys[r][q * 4 + 2] = f2tf(ya[i].z); Ys[r][q * 4 + 3] = f2tf(ya[i].w);
        }
#pragma unroll
        for (int i = 0; i < 8; i++) {
            int s = i * 128 + tid; int r = s >> 3, q = s & 7;
            Bs[r][q * 4 + 0] = f2tf(wb[i].x); Bs[r][q * 4 + 1] = f2tf(wb[i].y);
            Bs[r][q * 4 + 2] = f2tf(wb[i].z); Bs[r][q * 4 + 3] = f2tf(wb[i].w);
        }
        __syncthreads();
#pragma unroll
        for (int kk = 0; kk < 32; kk += 8) {
            uint32_t a[4][4];
#pragma unroll
            for (int mi = 0; mi < 4; mi++) {
                a[mi][0] = Ys[mi * 16 + lr][kk + lc];
                a[mi][1] = Ys[mi * 16 + 8 + lr][kk + lc];
                a[mi][2] = Ys[mi * 16 + lr][kk + 4 + lc];
                a[mi][3] = Ys[mi * 16 + 8 + lr][kk + 4 + lc];
            }
            uint32_t b[4][2];
#pragma unroll
            for (int ni = 0; ni < 4; ni++) {
                int nr = w * 32 + ni * 8 + lr;
                b[ni][0] = Bs[nr][kk + lc]; b[ni][1] = Bs[nr][kk + 4 + lc];
            }
#pragma unroll
            for (int mi = 0; mi < 4; mi++)
#pragma unroll
                for (int ni = 0; ni < 4; ni++) mma8(c[mi][ni], a[mi], b[ni]);
        }
        __syncthreads();
    }

#pragma unroll
    for (int mi = 0; mi < 4; mi++)
#pragma unroll
        for (int ni = 0; ni < 4; ni++) {
            int col = ht * 128 + w * 32 + ni * 8 + 2 * lc;
#pragma unroll
            for (int h = 0; h < 2; h++) {
                int row = mi * 16 + lr + h * 8;
                if (row < m_cnt) {
                    *(float2*)&g_Y2[(size_t)(base + row) * HDIM + col] =
                        make_float2(c[mi][ni][h * 2], c[mi][ni][h * 2 + 1]);
                }
            }
        }
}

// ---------------- combine: out[t] = sum of token's 4 slots ----------------
__global__ __launch_bounds__(256) void combine_kernel(float* __restrict__ out) {
    const int t = blockIdx.x;
    const int tid = threadIdx.x;
    const int s0 = g_slot[t * TOPK + 0], s1 = g_slot[t * TOPK + 1];
    const int s2 = g_slot[t * TOPK + 2], s3 = g_slot[t * TOPK + 3];
    const float* y0 = &g_Y2[(size_t)s0 * HDIM];
    const float* y1 = &g_Y2[(size_t)s1 * HDIM];
    const float* y2 = &g_Y2[(size_t)s2 * HDIM];
    const float* y3 = &g_Y2[(size_t)s3 * HDIM];
#pragma unroll
    for (int i = 0; i < 2; i++) {
        int h = (tid + i * 256) * 4;
        float4 a = *(const float4*)(y0 + h);
        float4 b = *(const float4*)(y1 + h);
        float4 cc = *(const float4*)(y2 + h);
        float4 d = *(const float4*)(y3 + h);
        float4 r;
        r.x = a.x + b.x + cc.x + d.x;
        r.y = a.y + b.y + cc.y + d.y;
        r.z = a.z + b.z + cc.z + d.z;
        r.w = a.w + b.w + cc.w + d.w;
        *(float4*)(out + (size_t)t * HDIM + h) = r;
    }
}

// ---------------- launch ----------------
extern "C" void kernel_launch(void* const* d_in, const int* in_sizes, int n_in,
                              void* d_out, int out_size) {
    const float* x    = (const float*)d_in[0];   // [1,1024,2048]
    const float* gw   = (const float*)d_in[1];   // [64,2048]
    const float* gup  = (const float*)d_in[2];   // [64,1536,2048]
    const float* down = (const float*)d_in[3];   // [64,2048,768]
    float* out = (float*)d_out;

    init_kernel<<<1, 64>>>();
    router_kernel<<<64, 256>>>(x, gw);
    topk_kernel<<<4, 256>>>();
    scan_kernel<<<1, 1>>>();
    fill_kernel<<<4, 256>>>();
    gemm1_kernel<<<dim3(12, 128), 128>>>(x, gup);
    gemm2_kernel<<<dim3(16, 128), 128>>>(down);
    combine_kernel<<<1024, 256>>>(out);
}

// round 3
// speedup vs baseline: 1.1134x; 1.1134x over previous
#include <cuda_runtime.h>
#include <cstdint>
#include <cstddef>

#define T_TOK 1024
#define HDIM  2048
#define IDIM  768
#define NEXP  64
#define TOPK  4
#define MT    64      // m-tile (tokens per expert tile)

// ---------------- static device scratch (no allocations) ----------------
__device__ float g_logits[T_TOK * NEXP];
__device__ int   g_counts[NEXP];
__device__ int   g_offs[NEXP];
__device__ int   g_cursor[NEXP];
__device__ int   g_topi[T_TOK * TOPK];
__device__ float g_topw[T_TOK * TOPK];
__device__ int   g_tok[T_TOK * TOPK];    // compact token list per expert
__device__ float g_wt[T_TOK * TOPK];     // route weight per slot
__device__ int   g_slot[T_TOK * TOPK];   // token -> its 4 slot indices
__device__ int   g_work[128];            // (e<<6)|mt
__device__ int   g_nwork;
__device__ float g_Y [(size_t)T_TOK * TOPK * IDIM];   // 12.6 MB
__device__ float g_Y2[(size_t)T_TOK * TOPK * HDIM];   // 33.6 MB

// ---------------- helpers ----------------
__device__ __forceinline__ uint32_t f2tf(float f) {
    uint32_t r;
    asm("cvt.rna.tf32.f32 %0, %1;" : "=r"(r) : "f"(f));
    return r;
}
__device__ __forceinline__ void mma8(float* c, const uint32_t* a, const uint32_t* b) {
    asm volatile(
        "mma.sync.aligned.m16n8k8.row.col.f32.tf32.tf32.f32 "
        "{%0,%1,%2,%3}, {%4,%5,%6,%7}, {%8,%9}, {%0,%1,%2,%3};"
        : "+f"(c[0]), "+f"(c[1]), "+f"(c[2]), "+f"(c[3])
        : "r"(a[0]), "r"(a[1]), "r"(a[2]), "r"(a[3]), "r"(b[0]), "r"(b[1]));
}

// ---------------- router: fp32 logits = X @ Gw^T (deterministic) ---------
// block 0 also zeroes the expert counters (consumed by topk, next launch).
__global__ __launch_bounds__(256) void router_kernel(const float* __restrict__ x,
                                                     const float* __restrict__ gw) {
    __shared__ float Xs[16][72];
    __shared__ float Wt[64][72];
    const int tt = blockIdx.x;          // 64 tiles of 16 tokens
    const int tid = threadIdx.x;
    if (tt == 0 && tid < NEXP) g_counts[tid] = 0;
    const int t = tid & 15, eg = tid >> 4;   // 16 expert groups of 4
    float acc[4] = {0.f, 0.f, 0.f, 0.f};

    for (int kc = 0; kc < HDIM; kc += 64) {
        {
            int r = tid >> 4, q = tid & 15;
            float4 v = *(const float4*)(x + (size_t)(tt * 16 + r) * HDIM + kc + q * 4);
            *(float4*)&Xs[r][q * 4] = v;
        }
#pragma unroll
        for (int it = 0; it < 4; it++) {
            int s = it * 256 + tid;
            int e = s >> 4, q = s & 15;
            float4 v = *(const float4*)(gw + (size_t)e * HDIM + kc + q * 4);
            *(float4*)&Wt[e][q * 4] = v;
        }
        __syncthreads();
#pragma unroll
        for (int k = 0; k < 64; k += 4) {
            float4 a = *(const float4*)&Xs[t][k];
#pragma unroll
            for (int j = 0; j < 4; j++) {
                float4 b = *(const float4*)&Wt[eg * 4 + j][k];
                acc[j] += a.x * b.x + a.y * b.y + a.z * b.z + a.w * b.w;
            }
        }
        __syncthreads();
    }
    int tok = tt * 16 + t;
#pragma unroll
    for (int j = 0; j < 4; j++) g_logits[tok * NEXP + eg * 4 + j] = acc[j];
}

// ---------- top-4 + softmax-over-top4 (== softmax -> topk -> renorm) -----
__global__ void topk_kernel() {
    int t = blockIdx.x * blockDim.x + threadIdx.x;
    if (t >= T_TOK) return;
    float v0 = -1e30f, v1 = -1e30f, v2 = -1e30f, v3 = -1e30f;
    int i0 = 0, i1 = 0, i2 = 0, i3 = 0;
    const float* L = &g_logits[t * NEXP];
    for (int e = 0; e < NEXP; e++) {
        float l = L[e];
        if (l > v3) {
            if (l > v2) {
                v3 = v2; i3 = i2;
                if (l > v1) {
                    v2 = v1; i2 = i1;
                    if (l > v0) { v1 = v0; i1 = i0; v0 = l; i0 = e; }
                    else        { v1 = l;  i1 = e; }
                } else { v2 = l; i2 = e; }
            } else { v3 = l; i3 = e; }
        }
    }
    float e0 = 1.f;
    float e1 = expf(v1 - v0), e2 = expf(v2 - v0), e3 = expf(v3 - v0);
    float inv = 1.f / (e0 + e1 + e2 + e3);
    int   ii[4] = {i0, i1, i2, i3};
    float ww[4] = {e0 * inv, e1 * inv, e2 * inv, e3 * inv};
#pragma unroll
    for (int j = 0; j < TOPK; j++) {
        g_topi[t * TOPK + j] = ii[j];
        g_topw[t * TOPK + j] = ww[j];
        atomicAdd(&g_counts[ii[j]], 1);
    }
}

// ---------------- scan: offsets + tile work list (parallel) ---------------
__global__ void scan_kernel() {
    __shared__ int cnt[NEXP], coff[NEXP], woff[NEXP];
    const int e = threadIdx.x;         // 64 threads
    cnt[e] = g_counts[e];
    __syncthreads();
    if (e == 0) {
        int off = 0, w = 0;
        for (int i = 0; i < NEXP; i++) {
            coff[i] = off; off += cnt[i];
            woff[i] = w;   w += (cnt[i] + MT - 1) / MT;
        }
        g_nwork = w;
    }
    __syncthreads();
    g_offs[e] = coff[e];
    g_cursor[e] = 0;
    const int tiles = (cnt[e] + MT - 1) / MT;
    for (int mt = 0; mt < tiles; mt++) g_work[woff[e] + mt] = (e << 6) | mt;
}

// ---------------- fill compact per-expert token/weight lists --------------
__global__ void fill_kernel() {
    int t = blockIdx.x * blockDim.x + threadIdx.x;
    if (t >= T_TOK) return;
#pragma unroll
    for (int j = 0; j < TOPK; j++) {
        int e = g_topi[t * TOPK + j];
        int p = atomicAdd(&g_cursor[e], 1);
        int idx = g_offs[e] + p;
        g_tok[idx] = t;
        g_wt[idx]  = g_topw[t * TOPK + j];
        g_slot[t * TOPK + j] = idx;
    }
}

// ------ GEMM1: Y[slot][0:768] = silu(X@Wg^T) * (X@Wu^T) * route_w, tf32 ---
// block = 128 thr (4 warps), C tile m64 x (gate64 + up64), K chunks of 32.
// Software pipelined: register prefetch of chunk k+1 issued before compute k.
__global__ __launch_bounds__(128, 2) void gemm1_kernel(const float* __restrict__ x,
                                                       const float* __restrict__ gup) {
    const int widx = blockIdx.y;
    if (widx >= g_nwork) return;
    const int jt = blockIdx.x;                 // 0..11
    const int packed = g_work[widx];
    const int e = packed >> 6, mt = packed & 63;
    const int n_e = g_counts[e];
    const int base = g_offs[e] + mt * MT;
    int m_cnt = n_e - mt * MT; if (m_cnt > MT) m_cnt = MT;

    __shared__ uint32_t Xs[64][36];
    __shared__ uint32_t Bg[64][36];
    __shared__ uint32_t Bu[64][36];
    __shared__ int   s_tok[64];
    __shared__ float s_wt[64];

    const int tid = threadIdx.x;
    const int w = tid >> 5, lane = tid & 31;
    if (tid < 64) {
        int tk = 0; float wt = 0.f;
        if (tid < m_cnt) { tk = g_tok[base + tid]; wt = g_wt[base + tid]; }
        s_tok[tid] = tk; s_wt[tid] = wt;
    }
    __syncthreads();

    float cg[4][2][4], cu[4][2][4];
#pragma unroll
    for (int a = 0; a < 4; a++)
#pragma unroll
        for (int b = 0; b < 2; b++)
#pragma unroll
            for (int c = 0; c < 4; c++) { cg[a][b][c] = 0.f; cu[a][b][c] = 0.f; }

    const float* wg = gup + (size_t)e * (2 * IDIM) * HDIM;
    const int lr = lane >> 2, lc = lane & 3;

    // fixed per-thread load/store addresses
    const float* xp[4]; uint32_t* xs[4];
#pragma unroll
    for (int i = 0; i < 4; i++) {
        int s = i * 128 + tid; int r = s >> 3, q = s & 7;
        xp[i] = x + (size_t)s_tok[r] * HDIM + q * 4;
        xs[i] = &Xs[r][q * 4];
    }
    const float* bp[8]; uint32_t* bs[8];
#pragma unroll
    for (int i = 0; i < 8; i++) {
        int s = i * 128 + tid; int r = s >> 3, q = s & 7;
        int jrow = (r < 64) ? (jt * 64 + r) : (IDIM + jt * 64 + (r - 64));
        bp[i] = wg + (size_t)jrow * HDIM + q * 4;
        bs[i] = (r < 64) ? &Bg[r][q * 4] : &Bu[r - 64][q * 4];
    }

    // prologue: chunk 0 into registers
    float4 xa[4], wa[8];
#pragma unroll
    for (int i = 0; i < 4; i++) xa[i] = *(const float4*)(xp[i]);
#pragma unroll
    for (int i = 0; i < 8; i++) wa[i] = *(const float4*)(bp[i]);

    for (int kc = 0; kc < HDIM; kc += 32) {
        __syncthreads();
#pragma unroll
        for (int i = 0; i < 4; i++) {
            xs[i][0] = f2tf(xa[i].x); xs[i][1] = f2tf(xa[i].y);
            xs[i][2] = f2tf(xa[i].z); xs[i][3] = f2tf(xa[i].w);
        }
#pragma unroll
        for (int i = 0; i < 8; i++) {
            bs[i][0] = f2tf(wa[i].x); bs[i][1] = f2tf(wa[i].y);
            bs[i][2] = f2tf(wa[i].z); bs[i][3] = f2tf(wa[i].w);
        }
        __syncthreads();
        if (kc + 32 < HDIM) {   // prefetch next chunk (overlaps with MMAs below)
#pragma unroll
            for (int i = 0; i < 4; i++) xa[i] = *(const float4*)(xp[i] + kc + 32);
#pragma unroll
            for (int i = 0; i < 8; i++) wa[i] = *(const float4*)(bp[i] + kc + 32);
        }
#pragma unroll
        for (int kk = 0; kk < 32; kk += 8) {
            uint32_t a[4][4];
#pragma unroll
            for (int mi = 0; mi < 4; mi++) {
                a[mi][0] = Xs[mi * 16 + lr][kk + lc];
                a[mi][1] = Xs[mi * 16 + 8 + lr][kk + lc];
                a[mi][2] = Xs[mi * 16 + lr][kk + 4 + lc];
                a[mi][3] = Xs[mi * 16 + 8 + lr][kk + 4 + lc];
            }
            uint32_t bgf[2][2], buf[2][2];
#pragma unroll
            for (int ni = 0; ni < 2; ni++) {
                int nr = w * 16 + ni * 8 + lr;
                bgf[ni][0] = Bg[nr][kk + lc]; bgf[ni][1] = Bg[nr][kk + 4 + lc];
                buf[ni][0] = Bu[nr][kk + lc]; buf[ni][1] = Bu[nr][kk + 4 + lc];
            }
#pragma unroll
            for (int mi = 0; mi < 4; mi++)
#pragma unroll
                for (int ni = 0; ni < 2; ni++) {
                    mma8(cg[mi][ni], a[mi], bgf[ni]);
                    mma8(cu[mi][ni], a[mi], buf[ni]);
                }
        }
    }

    // epilogue: silu(g)*u*route_w -> Y
#pragma unroll
    for (int mi = 0; mi < 4; mi++)
#pragma unroll
        for (int ni = 0; ni < 2; ni++) {
            int col = jt * 64 + w * 16 + ni * 8 + 2 * lc;
#pragma unroll
            for (int h = 0; h < 2; h++) {
                int row = mi * 16 + lr + h * 8;
                if (row < m_cnt) {
                    float wt = s_wt[row];
                    float g0 = cg[mi][ni][h * 2],     g1 = cg[mi][ni][h * 2 + 1];
                    float u0 = cu[mi][ni][h * 2],     u1 = cu[mi][ni][h * 2 + 1];
                    float y0 = g0 / (1.f + __expf(-g0)) * u0 * wt;
                    float y1 = g1 / (1.f + __expf(-g1)) * u1 * wt;
                    *(float2*)&g_Y[(size_t)(base + row) * IDIM + col] = make_float2(y0, y1);
                }
            }
        }
}

// ------ GEMM2: Y2[slot][0:2048] = Y @ W2^T, tf32, pipelined ---------------
// block = 128 thr (4 warps), C tile m64 x n128, K = 768 in chunks of 32
__global__ __launch_bounds__(128, 2) void gemm2_kernel(const float* __restrict__ down) {
    const int widx = blockIdx.y;
    if (widx >= g_nwork) return;
    const int ht = blockIdx.x;                 // 0..15
    const int packed = g_work[widx];
    const int e = packed >> 6, mt = packed & 63;
    const int n_e = g_counts[e];
    const int base = g_offs[e] + mt * MT;
    int m_cnt = n_e - mt * MT; if (m_cnt > MT) m_cnt = MT;

    __shared__ uint32_t Ys[64][36];
    __shared__ uint32_t Bs[128][36];

    const int tid = threadIdx.x;
    const int w = tid >> 5, lane = tid & 31;
    const int lr = lane >> 2, lc = lane & 3;

    float c[4][4][4];
#pragma unroll
    for (int a = 0; a < 4; a++)
#pragma unroll
        for (int b = 0; b < 4; b++)
#pragma unroll
            for (int k = 0; k < 4; k++) c[a][b][k] = 0.f;

    const float* wd = down + (size_t)e * HDIM * IDIM;

    // fixed per-thread addresses
    const float* yp[4]; uint32_t* ys[4];
#pragma unroll
    for (int i = 0; i < 4; i++) {
        int s = i * 128 + tid; int r = s >> 3, q = s & 7;
        int slot = base + r; if (slot > T_TOK * TOPK - 1) slot = T_TOK * TOPK - 1;
        yp[i] = &g_Y[(size_t)slot * IDIM + q * 4];
        ys[i] = &Ys[r][q * 4];
    }
    const float* bp[8]; uint32_t* bs[8];
#pragma unroll
    for (int i = 0; i < 8; i++) {
        int s = i * 128 + tid; int r = s >> 3, q = s & 7;
        bp[i] = wd + (size_t)(ht * 128 + r) * IDIM + q * 4;
        bs[i] = &Bs[r][q * 4];
    }

    float4 ya[4], wa[8];
#pragma unroll
    for (int i = 0; i < 4; i++) ya[i] = *(const float4*)(yp[i]);
#pragma unroll
    for (int i = 0; i < 8; i++) wa[i] = *(const float4*)(bp[i]);

    for (int kc = 0; kc < IDIM; kc += 32) {
        __syncthreads();
#pragma unroll
        for (int i = 0; i < 4; i++) {
            ys[i][0] = f2tf(ya[i].x); ys[i][1] = f2tf(ya[i].y);
            ys[i][2] = f2tf(ya[i].z); ys[i][3] = f2tf(ya[i].w);
        }
#pragma unroll
        for (int i = 0; i < 8; i++) {
            bs[i][0] = f2tf(wa[i].x); bs[i][1] = f2tf(wa[i].y);
            bs[i][2] = f2tf(wa[i].z); bs[i][3] = f2tf(wa[i].w);
        }
        __syncthreads();
        if (kc + 32 < IDIM) {   // prefetch next chunk
#pragma unroll
            for (int i = 0; i < 4; i++) ya[i] = *(const float4*)(yp[i] + kc + 32);
#pragma unroll
            for (int i = 0; i < 8; i++) wa[i] = *(const float4*)(bp[i] + kc + 32);
        }
#pragma unroll
        for (int kk = 0; kk < 32; kk += 8) {
            uint32_t a[4][4];
#pragma unroll
            for (int mi = 0; mi < 4; mi++) {
                a[mi][0] = Ys[mi * 16 + lr][kk + lc];
                a[mi][1] = Ys[mi * 16 + 8 + lr][kk + lc];
                a[mi][2] = Ys[mi * 16 + lr][kk + 4 + lc];
                a[mi][3] = Ys[mi * 16 + 8 + lr][kk + 4 + lc];
            }
            uint32_t b[4][2];
#pragma unroll
            for (int ni = 0; ni < 4; ni++) {
                int nr = w * 32 + ni * 8 + lr;
                b[ni][0] = Bs[nr][kk + lc]; b[ni][1] = Bs[nr][kk + 4 + lc];
            }
#pragma unroll
            for (int mi = 0; mi < 4; mi++)
#pragma unroll
                for (int ni = 0; ni < 4; ni++) mma8(c[mi][ni], a[mi], b[ni]);
        }
    }

#pragma unroll
    for (int mi = 0; mi < 4; mi++)
#pragma unroll
        for (int ni = 0; ni < 4; ni++) {
            int col = ht * 128 + w * 32 + ni * 8 + 2 * lc;
#pragma unroll
            for (int h = 0; h < 2; h++) {
                int row = mi * 16 + lr + h * 8;
                if (row < m_cnt) {
                    *(float2*)&g_Y2[(size_t)(base + row) * HDIM + col] =
                        make_float2(c[mi][ni][h * 2], c[mi][ni][h * 2 + 1]);
                }
            }
        }
}

// ---------------- combine: out[t] = sum of token's 4 slots ----------------
__global__ __launch_bounds__(256) void combine_kernel(float* __restrict__ out) {
    const int t = blockIdx.x;
    const int tid = threadIdx.x;
    const int s0 = g_slot[t * TOPK + 0], s1 = g_slot[t * TOPK + 1];
    const int s2 = g_slot[t * TOPK + 2], s3 = g_slot[t * TOPK + 3];
    const float* y0 = &g_Y2[(size_t)s0 * HDIM];
    const float* y1 = &g_Y2[(size_t)s1 * HDIM];
    const float* y2 = &g_Y2[(size_t)s2 * HDIM];
    const float* y3 = &g_Y2[(size_t)s3 * HDIM];
#pragma unroll
    for (int i = 0; i < 2; i++) {
        int h = (tid + i * 256) * 4;
        float4 a = *(const float4*)(y0 + h);
        float4 b = *(const float4*)(y1 + h);
        float4 cc = *(const float4*)(y2 + h);
        float4 d = *(const float4*)(y3 + h);
        float4 r;
        r.x = a.x + b.x + cc.x + d.x;
        r.y = a.y + b.y + cc.y + d.y;
        r.z = a.z + b.z + cc.z + d.z;
        r.w = a.w + b.w + cc.w + d.w;
        *(float4*)(out + (size_t)t * HDIM + h) = r;
    }
}

// ---------------- launch ----------------
extern "C" void kernel_launch(void* const* d_in, const int* in_sizes, int n_in,
                              void* d_out, int out_size) {
    const float* x    = (const float*)d_in[0];   // [1,1024,2048]
    const float* gw   = (const float*)d_in[1];   // [64,2048]
    const float* gup  = (const float*)d_in[2];   // [64,1536,2048]
    const float* down = (const float*)d_in[3];   // [64,2048,768]
    float* out = (float*)d_out;

    router_kernel<<<64, 256>>>(x, gw);
    topk_kernel<<<4, 256>>>();
    scan_kernel<<<1, 64>>>();
    fill_kernel<<<4, 256>>>();
    gemm1_kernel<<<dim3(12, 128), 128>>>(x, gup);
    gemm2_kernel<<<dim3(16, 128), 128>>>(down);
    combine_kernel<<<1024, 256>>>(out);
}